// round 10
// baseline (speedup 1.0000x reference)
#include <cuda_runtime.h>
#include <math.h>
#include <stdint.h>

#define NN 20000
#define TT 20
#define FF 128
#define HH 128
#define GHD 128
#define NHEADS 4
#define NCLS 10
#define EE 640000
#define EN (EE + NN)
#define NROWS (NN * TT)           // 400000
#define PRE_STRIDE ((size_t)NROWS * 512)

// ---------------- scratch (device globals: allocation-free rule) ----------------
__device__ float g_hcat[NN * 256];
__device__ float g_xh1[NN * 512];
__device__ float g_al1s[NN * 4];
__device__ float g_al1d[NN * 4];
__device__ float g_agg1[NN * 512];
__device__ float g_xh2[NN * 128];
__device__ float g_al2s[NN];
__device__ float g_al2d[NN];
// LSTM weights tf32-rounded: [dir][k=256][gatecol=512] (k<128: Wih, k>=128: Whh)
__device__ float g_Wt[2 * 256 * 512];
// GAT weights tf32-rounded, [k][col]
__device__ float g_W1t[256 * 512];
__device__ float g_W2t[512 * 128];
// precomputed input-gate preactivations: [dir][n*T + t][512]
__device__ float g_pre[2 * NROWS * 512];
// CSR by dst
__device__ int g_cnt[NN];
__device__ int g_base[NN + 1];
__device__ int g_srcs[EN];

__device__ __forceinline__ float lrelu(float x) { return x > 0.0f ? x : 0.2f * x; }
__device__ __forceinline__ float rna_tf32(float v) {
    float o; asm("cvt.rna.tf32.f32 %0, %1;" : "=f"(o) : "f"(v)); return o;
}
__device__ __forceinline__ float fsig(float x) { return __fdividef(1.0f, 1.0f + __expf(-x)); }
__device__ __forceinline__ float ftanh(float x) {
    return __fdividef(2.0f, 1.0f + __expf(-2.0f * x)) - 1.0f;
}
__device__ __forceinline__ uint32_t smem_u32(const void* p) {
    uint32_t a;
    asm("{ .reg .u64 t; cvta.to.shared.u64 t, %1; cvt.u32.u64 %0, t; }" : "=r"(a) : "l"(p));
    return a;
}
#define CP16(dst, src)    asm volatile("cp.async.cg.shared.global [%0], [%1], 16;" :: "r"(dst), "l"(src))
#define CP_COMMIT()       asm volatile("cp.async.commit_group;" ::: "memory")
#define CP_WAIT0()        asm volatile("cp.async.wait_group 0;" ::: "memory")

// m16n8k8 tf32 mma: D += A*B. A row-major, B col-major (k x n).
__device__ __forceinline__ void mma_tf32(float* d, uint32_t a0, uint32_t a1, uint32_t a2,
                                         uint32_t a3, uint32_t b0, uint32_t b1) {
    asm volatile("mma.sync.aligned.m16n8k8.row.col.f32.tf32.tf32.f32 "
                 "{%0,%1,%2,%3}, {%4,%5,%6,%7}, {%8,%9}, {%0,%1,%2,%3};"
                 : "+f"(d[0]), "+f"(d[1]), "+f"(d[2]), "+f"(d[3])
                 : "r"(a0), "r"(a1), "r"(a2), "r"(a3), "r"(b0), "r"(b1));
}

// ---------------- weight prep ----------------
__global__ void prep_w(const float* __restrict__ Wih_f, const float* __restrict__ Whh_f,
                       const float* __restrict__ Wih_b, const float* __restrict__ Whh_b) {
    const int idx = blockIdx.x * blockDim.x + threadIdx.x;
    if (idx >= 2 * 256 * 512) return;
    const int dir = idx >> 17;
    const int rem = idx & 131071;
    const int k = rem >> 9;
    const int c = rem & 511;
    const float* Ws = dir ? (k < 128 ? Wih_b : Whh_b) : (k < 128 ? Wih_f : Whh_f);
    g_Wt[idx] = rna_tf32(Ws[(size_t)c * 128 + (k & 127)]);
}
__global__ void prep_gw(const float* __restrict__ W1, const float* __restrict__ W2) {
    const int idx = blockIdx.x * blockDim.x + threadIdx.x;
    if (idx < 256 * 512) {
        const int k = idx >> 9, c = idx & 511;
        g_W1t[idx] = rna_tf32(W1[(size_t)c * 256 + k]);
    }
    const int j = idx - 256 * 512;
    if (j >= 0 && j < 512 * 128) {
        const int k = j >> 7, c = j & 127;
        g_W2t[j] = rna_tf32(W2[(size_t)c * 512 + k]);
    }
}

// ---------------- CSR build (edges + self loops, grouped by dst) ----------------
__global__ void csr_zero() {
    const int i = blockIdx.x * blockDim.x + threadIdx.x;
    if (i < NN) g_cnt[i] = 0;
}
__global__ void csr_hist(const int* __restrict__ ei) {
    const int e = blockIdx.x * blockDim.x + threadIdx.x;
    if (e >= EN) return;
    const int d = (e < EE) ? ei[EE + e] : (e - EE);
    atomicAdd(&g_cnt[d], 1);
}
__global__ void __launch_bounds__(1024, 1) csr_scan() {
    __shared__ int ps[1024];
    const int tid = threadIdx.x;
    const int base = tid * 20;
    int local[20];
    int s = 0;
#pragma unroll
    for (int i = 0; i < 20; i++) {
        const int idx = base + i;
        const int c = (idx < NN) ? g_cnt[idx] : 0;
        local[i] = s;
        s += c;
    }
    ps[tid] = s;
    __syncthreads();
    for (int off = 1; off < 1024; off <<= 1) {
        int v = (tid >= off) ? ps[tid - off] : 0;
        __syncthreads();
        ps[tid] += v;
        __syncthreads();
    }
    const int excl = (tid == 0) ? 0 : ps[tid - 1];
#pragma unroll
    for (int i = 0; i < 20; i++) {
        const int idx = base + i;
        if (idx < NN) g_base[idx] = excl + local[i];
    }
    if (tid == 1023) g_base[NN] = ps[1023];
    __syncthreads();
    for (int i = tid; i < NN; i += 1024) g_cnt[i] = g_base[i];  // cursor
}
__global__ void csr_scatter(const int* __restrict__ ei) {
    const int e = blockIdx.x * blockDim.x + threadIdx.x;
    if (e >= EN) return;
    int s, d;
    if (e < EE) { s = ei[e]; d = ei[EE + e]; } else { s = d = e - EE; }
    const int pos = atomicAdd(&g_cnt[d], 1);
    g_srcs[pos] = s;
}

// ---------------- pre-GEMM: g_pre[dir] = x(400k x 128) @ Wih_dir(128 x 512) ----------------
// 64 rows/CTA, 512 threads. grid (6250, 2). No recurrence -> fully parallel.
#define PSA 132
#define PSB 520
#define PBO 16640
#define PRE_SMEM ((64 * PSA + 2 * PBO) * 4)

__global__ void __launch_bounds__(512, 1) pre_gemm(const float* __restrict__ x)
{
    extern __shared__ float sm[];
    float* const A_s = sm;
    float* const B_s = sm + 64 * PSA;
    const uint32_t B_u = smem_u32(B_s);

    const int tid = threadIdx.x;
    const int wid = tid >> 5, lane = tid & 31;
    const int g = lane >> 2, ctg = lane & 3;
    const int rg = wid >> 2, q = wid & 3;
    const int rA = rg * 16 + g, rB = rA + 8;
    const int row0 = blockIdx.x * 64;
    const int dir = blockIdx.y;
    const float* __restrict__ Wt = g_Wt + (size_t)dir * 131072;   // rows 0..127 = Wih
    float* __restrict__ C = g_pre + (size_t)dir * PRE_STRIDE;

    // stage A (x rows, tf32-rounded)
    for (int idx = tid; idx < 64 * 32; idx += 512) {
        const int row = idx >> 5, c4 = idx & 31;
        const float4 v = *(const float4*)(x + (size_t)(row0 + row) * 128 + c4 * 4);
        float4 r;
        r.x = rna_tf32(v.x); r.y = rna_tf32(v.y);
        r.z = rna_tf32(v.z); r.w = rna_tf32(v.w);
        *(float4*)(A_s + row * PSA + c4 * 4) = r;
    }

    float acc[4][4][4];
#pragma unroll
    for (int gi = 0; gi < 4; gi++)
#pragma unroll
        for (int ni = 0; ni < 4; ni++)
#pragma unroll
            for (int p = 0; p < 4; p++) acc[gi][ni][p] = 0.0f;

    // prefetch B chunk 0 (32 rows x 512)
#pragma unroll
    for (int j = 0; j < 8; j++) {
        const int idx = j * 512 + tid;
        const int row = idx >> 7, f4 = idx & 127;
        CP16(B_u + (row * PSB + f4 * 4) * 4, Wt + row * 512 + f4 * 4);
    }
    CP_COMMIT();

    for (int kc = 0; kc < 4; kc++) {
        CP_WAIT0();
        __syncthreads();
        if (kc < 3) {
            const int nb = (kc + 1) & 1;
            const float* src = Wt + (kc + 1) * 16384;
#pragma unroll
            for (int j = 0; j < 8; j++) {
                const int idx = j * 512 + tid;
                const int row = idx >> 7, f4 = idx & 127;
                CP16(B_u + (nb * PBO + row * PSB + f4 * 4) * 4, src + row * 512 + f4 * 4);
            }
            CP_COMMIT();
        }
        const float* Bb = B_s + (kc & 1) * PBO;
#pragma unroll
        for (int ks = 0; ks < 4; ks++) {
            const int k = kc * 32 + ks * 8;
            const uint32_t a0 = __float_as_uint(A_s[rA * PSA + k + ctg]);
            const uint32_t a1 = __float_as_uint(A_s[rB * PSA + k + ctg]);
            const uint32_t a2 = __float_as_uint(A_s[rA * PSA + k + ctg + 4]);
            const uint32_t a3 = __float_as_uint(A_s[rB * PSA + k + ctg + 4]);
            const float* B0 = Bb + (ks * 8 + ctg) * PSB + g;
            const float* B4 = B0 + 4 * PSB;
#pragma unroll
            for (int gi = 0; gi < 4; gi++) {
#pragma unroll
                for (int ni = 0; ni < 4; ni++) {
                    const int n0 = gi * 128 + q * 32 + ni * 8;
                    const uint32_t b0 = __float_as_uint(B0[n0]);
                    const uint32_t b1 = __float_as_uint(B4[n0]);
                    mma_tf32(acc[gi][ni], a0, a1, a2, a3, b0, b1);
                }
            }
        }
        __syncthreads();
    }

#pragma unroll
    for (int gi = 0; gi < 4; gi++)
#pragma unroll
        for (int ni = 0; ni < 4; ni++) {
            const int n0 = gi * 128 + q * 32 + ni * 8 + 2 * ctg;
            *(float2*)(C + (size_t)(row0 + rA) * 512 + n0) =
                make_float2(acc[gi][ni][0], acc[gi][ni][1]);
            *(float2*)(C + (size_t)(row0 + rB) * 512 + n0) =
                make_float2(acc[gi][ni][2], acc[gi][ni][3]);
        }
}

// ---------------- recurrent LSTM: gates = pre[:,t,:] + h @ Whh^T ----------------
// 64 seqs/CTA, 512 threads, K=128 (h only). acc initialized from g_pre.
#define RSA 132
#define RSB 520
#define RBO 16640
#define RBIAS (64 * RSA + 2 * RBO)       // 41728
#define RLEN  (RBIAS + 512)              // 42240
#define REC_SMEM ((RLEN + 64) * 4)       // 169216 B

__global__ void __launch_bounds__(512, 1) lstm_rec(
    const int* __restrict__ lengths,
    const float* __restrict__ b_f, const float* __restrict__ b_b)
{
    extern __shared__ float sm[];
    float* const A_s   = sm;             // h [64][132]
    float* const B_s   = sm + 64 * RSA;
    float* const biasf = sm + RBIAS;
    int*   const len_s = (int*)(sm + RLEN);
    const uint32_t B_u = smem_u32(B_s);

    const int tid = threadIdx.x;
    const int wid = tid >> 5, lane = tid & 31;
    const int g = lane >> 2, ctg = lane & 3;
    const int rg = wid >> 2, q = wid & 3;
    const int rA = rg * 16 + g, rB = rA + 8;
    const int dir = blockIdx.y;
    const int seq0 = blockIdx.x * 64;
    const float* __restrict__ bb = dir ? b_b : b_f;
    const float* __restrict__ Wr = g_Wt + (size_t)dir * 131072 + 65536;  // Whh rows
    const float* __restrict__ pre_d = g_pre + (size_t)dir * PRE_STRIDE;

    biasf[tid] = bb[tid];
    if (tid < 64) len_s[tid] = lengths[min(seq0 + tid, NN - 1)];
    for (int i = tid; i < 64 * RSA; i += 512) A_s[i] = 0.0f;  // h0 = 0
    __syncthreads();

    const int lenA = len_s[rA], lenB = len_s[rB];
    const size_t sqA = (size_t)min(seq0 + rA, NN - 1);
    const size_t sqB = (size_t)min(seq0 + rB, NN - 1);

    float acc[4][4][4];
    float cst[4][4];
#pragma unroll
    for (int ni = 0; ni < 4; ni++)
#pragma unroll
        for (int p = 0; p < 4; p++) cst[ni][p] = 0.0f;

    for (int t = 0; t < TT; t++) {
        // acc init from pre (per-row time index; reversed dir reads backwards)
        const int ttvA = dir ? max(lenA - 1 - t, 0) : t;
        const int ttvB = dir ? max(lenB - 1 - t, 0) : t;
        const float* pA = pre_d + (sqA * TT + ttvA) * 512;
        const float* pB = pre_d + (sqB * TT + ttvB) * 512;
#pragma unroll
        for (int gi = 0; gi < 4; gi++)
#pragma unroll
            for (int ni = 0; ni < 4; ni++) {
                const int n0 = gi * 128 + q * 32 + ni * 8 + 2 * ctg;
                const float2 va = *(const float2*)(pA + n0);
                const float2 vb = *(const float2*)(pB + n0);
                acc[gi][ni][0] = va.x; acc[gi][ni][1] = va.y;
                acc[gi][ni][2] = vb.x; acc[gi][ni][3] = vb.y;
            }

        // prefetch Whh chunk 0
#pragma unroll
        for (int j = 0; j < 8; j++) {
            const int idx = j * 512 + tid;
            const int row = idx >> 7, f4 = idx & 127;
            CP16(B_u + (row * RSB + f4 * 4) * 4, Wr + row * 512 + f4 * 4);
        }
        CP_COMMIT();

        for (int kc = 0; kc < 4; kc++) {
            CP_WAIT0();
            __syncthreads();
            if (kc < 3) {
                const int nb = (kc + 1) & 1;
                const float* src = Wr + (kc + 1) * 16384;
#pragma unroll
                for (int j = 0; j < 8; j++) {
                    const int idx = j * 512 + tid;
                    const int row = idx >> 7, f4 = idx & 127;
                    CP16(B_u + (nb * RBO + row * RSB + f4 * 4) * 4, src + row * 512 + f4 * 4);
                }
                CP_COMMIT();
            }
            const float* Bb = B_s + (kc & 1) * RBO;
#pragma unroll
            for (int ks = 0; ks < 4; ks++) {
                const int k = kc * 32 + ks * 8;
                const uint32_t a0 = __float_as_uint(A_s[rA * RSA + k + ctg]);
                const uint32_t a1 = __float_as_uint(A_s[rB * RSA + k + ctg]);
                const uint32_t a2 = __float_as_uint(A_s[rA * RSA + k + ctg + 4]);
                const uint32_t a3 = __float_as_uint(A_s[rB * RSA + k + ctg + 4]);
                const float* B0 = Bb + (ks * 8 + ctg) * RSB + g;
                const float* B4 = B0 + 4 * RSB;
#pragma unroll
                for (int gi = 0; gi < 4; gi++) {
#pragma unroll
                    for (int ni = 0; ni < 4; ni++) {
                        const int n0 = gi * 128 + q * 32 + ni * 8;
                        const uint32_t b0 = __float_as_uint(B0[n0]);
                        const uint32_t b1 = __float_as_uint(B4[n0]);
                        mma_tf32(acc[gi][ni], a0, a1, a2, a3, b0, b1);
                    }
                }
            }
        }

        __syncthreads();   // mma reads of h done before writeback

        // cell math (register-local), h writeback
#pragma unroll
        for (int ni = 0; ni < 4; ni++) {
            const int hc0 = q * 32 + ni * 8 + 2 * ctg;
#pragma unroll
            for (int p = 0; p < 4; p++) {
                const int col = hc0 + (p & 1);
                const int row = (p < 2) ? rA : rB;
                const bool act = t < ((p < 2) ? lenA : lenB);
                const float pi = acc[0][ni][p] + biasf[col];
                const float pf = acc[1][ni][p] + biasf[128 + col];
                const float pg = acc[2][ni][p] + biasf[256 + col];
                const float po = acc[3][ni][p] + biasf[384 + col];
                const float cn = fsig(pf) * cst[ni][p] + fsig(pi) * ftanh(pg);
                const float hn = fsig(po) * ftanh(cn);
                if (act) {
                    cst[ni][p] = cn;
                    A_s[row * RSA + col] = rna_tf32(hn);
                }
            }
        }
        __syncthreads();
    }

    // final frozen h -> g_hcat
    for (int i = tid; i < 64 * 32; i += 512) {
        const int row = i >> 5, f4 = i & 31;
        const int seq = seq0 + row;
        if (seq < NN) {
            const float4 v = *(const float4*)(A_s + row * RSA + f4 * 4);
            *(float4*)(g_hcat + (size_t)seq * 256 + dir * 128 + f4 * 4) = v;
        }
    }
}

// ---------------- generic tensor GEMM: C[N][COLS] = A[N][KTOT] @ Bt[KTOT][COLS] ----------------
template <int KTOT, int COLS>
__global__ void __launch_bounds__(512, 1) gemm_mma(
    const float* __restrict__ A, const float* __restrict__ Bt, float* __restrict__ C)
{
    constexpr int SA2 = KTOT + 4;
    constexpr int SB2 = COLS + 8;
    constexpr int GI = COLS / 128;
    constexpr int BO2 = 32 * SB2;
    extern __shared__ float sm[];
    float* const A_s = sm;
    float* const B_s = sm + 64 * SA2;
    const uint32_t B_u = smem_u32(B_s);

    const int tid = threadIdx.x;
    const int wid = tid >> 5, lane = tid & 31;
    const int g = lane >> 2, ctg = lane & 3;
    const int r0 = (wid >> 2) * 16;
    const int q = wid & 3;
    const int rA = r0 + g, rB = r0 + g + 8;
    const int row0 = blockIdx.x * 64;

    constexpr int K4 = KTOT / 4;
    for (int idx = tid; idx < 64 * K4; idx += 512) {
        const int row = idx / K4, c4 = idx % K4;
        const int sq = min(row0 + row, NN - 1);
        const float4 v = *(const float4*)(A + (size_t)sq * KTOT + c4 * 4);
        float4 r;
        r.x = rna_tf32(v.x); r.y = rna_tf32(v.y);
        r.z = rna_tf32(v.z); r.w = rna_tf32(v.w);
        *(float4*)(A_s + row * SA2 + c4 * 4) = r;
    }

    float acc[GI][4][4];
#pragma unroll
    for (int gi = 0; gi < GI; gi++)
#pragma unroll
        for (int ni = 0; ni < 4; ni++)
#pragma unroll
            for (int p = 0; p < 4; p++) acc[gi][ni][p] = 0.0f;

    constexpr int NC = KTOT / 32;
    constexpr int C4 = COLS / 4;
    for (int j = tid; j < 8 * COLS; j += 512) {
        const int row = j / C4, c4 = j % C4;
        CP16(B_u + (row * SB2 + c4 * 4) * 4, Bt + (size_t)row * COLS + c4 * 4);
    }
    CP_COMMIT();

    for (int kc = 0; kc < NC; kc++) {
        CP_WAIT0();
        __syncthreads();
        if (kc < NC - 1) {
            const int nb = (kc + 1) & 1;
            const float* src = Bt + (size_t)(kc + 1) * 32 * COLS;
            for (int j = tid; j < 8 * COLS; j += 512) {
                const int row = j / C4, c4 = j % C4;
                CP16(B_u + (nb * BO2 + row * SB2 + c4 * 4) * 4, src + (size_t)row * COLS + c4 * 4);
            }
            CP_COMMIT();
        }
        const float* Bb = B_s + (kc & 1) * BO2;
#pragma unroll
        for (int ks = 0; ks < 4; ks++) {
            const int k = kc * 32 + ks * 8;
            const uint32_t a0 = __float_as_uint(A_s[rA * SA2 + k + ctg]);
            const uint32_t a1 = __float_as_uint(A_s[rB * SA2 + k + ctg]);
            const uint32_t a2 = __float_as_uint(A_s[rA * SA2 + k + ctg + 4]);
            const uint32_t a3 = __float_as_uint(A_s[rB * SA2 + k + ctg + 4]);
            const float* B0 = Bb + (ks * 8 + ctg) * SB2 + g;
            const float* B4 = B0 + 4 * SB2;
#pragma unroll
            for (int gi = 0; gi < GI; gi++) {
#pragma unroll
                for (int ni = 0; ni < 4; ni++) {
                    const int n0 = gi * 128 + q * 32 + ni * 8;
                    const uint32_t b0 = __float_as_uint(B0[n0]);
                    const uint32_t b1 = __float_as_uint(B4[n0]);
                    mma_tf32(acc[gi][ni], a0, a1, a2, a3, b0, b1);
                }
            }
        }
    }

#pragma unroll
    for (int gi = 0; gi < GI; gi++)
#pragma unroll
        for (int ni = 0; ni < 4; ni++) {
            const int n0 = gi * 128 + q * 32 + ni * 8 + 2 * ctg;
            if (row0 + rA < NN)
                *(float2*)(C + (size_t)(row0 + rA) * COLS + n0) =
                    make_float2(acc[gi][ni][0], acc[gi][ni][1]);
            if (row0 + rB < NN)
                *(float2*)(C + (size_t)(row0 + rB) * COLS + n0) =
                    make_float2(acc[gi][ni][2], acc[gi][ni][3]);
        }
}

// ---------------- GAT attention-logit projections (warp per (node, head)) ----------------
template <int NH>
__global__ void gat_al(const float* __restrict__ xh, const float* __restrict__ asrc,
                       const float* __restrict__ adst, float* __restrict__ als,
                       float* __restrict__ ald)
{
    const int w = (blockIdx.x * blockDim.x + threadIdx.x) >> 5;
    const int lane = threadIdx.x & 31;
    if (w >= NN * NH) return;
    const int n = w / NH, h = w % NH;
    const float4 v  = *(const float4*)(xh + (size_t)n * (NH * GHD) + h * GHD + lane * 4);
    const float4 s4 = *(const float4*)(asrc + h * GHD + lane * 4);
    const float4 d4 = *(const float4*)(adst + h * GHD + lane * 4);
    float s = v.x * s4.x + v.y * s4.y + v.z * s4.z + v.w * s4.w;
    float d = v.x * d4.x + v.y * d4.y + v.z * d4.z + v.w * d4.w;
#pragma unroll
    for (int o = 16; o > 0; o >>= 1) {
        s += __shfl_xor_sync(0xffffffffu, s, o);
        d += __shfl_xor_sync(0xffffffffu, d, o);
    }
    if (lane == 0) { als[w] = s; ald[w] = d; }
}

// ---------------- layer-1 gather: warp per (dst, head), lane-parallel edge prologue ----------------
__global__ void gat_gather4(const float* __restrict__ bias1) {
    const int w = (blockIdx.x * blockDim.x + threadIdx.x) >> 5;
    const int lane = threadIdx.x & 31;
    if (w >= NN * NHEADS) return;
    const int d = w >> 2, h = w & 3;
    const float aldv = g_al1d[d * 4 + h];
    const int beg = g_base[d], end = g_base[d + 1];
    float ax = 0.0f, ay = 0.0f, az = 0.0f, aw = 0.0f, denp = 0.0f;
    for (int eb = beg; eb < end; eb += 32) {
        const int ne = end - eb;
        int sl = 0; float eel = 0.0f;
        if (lane < ne) {
            sl = g_srcs[eb + lane];
            eel = __expf(lrelu(g_al1s[sl * 4 + h] + aldv));
        }
        denp += eel;
        const int m = min(ne, 32);
#pragma unroll 4
        for (int j = 0; j < m; j++) {
            const int s = __shfl_sync(0xffffffffu, sl, j);
            const float ee = __shfl_sync(0xffffffffu, eel, j);
            const float4 v = *(const float4*)(g_xh1 + (size_t)s * 512 + h * GHD + lane * 4);
            ax += ee * v.x; ay += ee * v.y; az += ee * v.z; aw += ee * v.w;
        }
    }
    float den = denp;
#pragma unroll
    for (int o = 16; o > 0; o >>= 1) den += __shfl_xor_sync(0xffffffffu, den, o);
    const float inv = __fdividef(1.0f, den + 1e-16f);
    const float4 b = *(const float4*)(bias1 + h * GHD + lane * 4);
    float4 o;
    o.x = fmaxf(ax * inv + b.x, 0.0f);
    o.y = fmaxf(ay * inv + b.y, 0.0f);
    o.z = fmaxf(az * inv + b.z, 0.0f);
    o.w = fmaxf(aw * inv + b.w, 0.0f);
    *(float4*)(g_agg1 + (size_t)d * 512 + h * GHD + lane * 4) = o;
}

// ---------------- layer-2 gather + fused FC: warp per dst ----------------
__global__ void gat_gather1_fc(const float* __restrict__ bias2,
                               const float* __restrict__ Wfc, const float* __restrict__ bfc,
                               float* __restrict__ out) {
    const int w = (blockIdx.x * blockDim.x + threadIdx.x) >> 5;
    const int lane = threadIdx.x & 31;
    if (w >= NN) return;
    const int d = w;
    const float aldv = g_al2d[d];
    const int beg = g_base[d], end = g_base[d + 1];
    float ax = 0.0f, ay = 0.0f, az = 0.0f, aw = 0.0f, denp = 0.0f;
    for (int eb = beg; eb < end; eb += 32) {
        const int ne = end - eb;
        int sl = 0; float eel = 0.0f;
        if (lane < ne) {
            sl = g_srcs[eb + lane];
            eel = __expf(lrelu(g_al2s[sl] + aldv));
        }
        denp += eel;
        const int m = min(ne, 32);
#pragma unroll 4
        for (int j = 0; j < m; j++) {
            const int s = __shfl_sync(0xffffffffu, sl, j);
            const float ee = __shfl_sync(0xffffffffu, eel, j);
            const float4 v = *(const float4*)(g_xh2 + (size_t)s * 128 + lane * 4);
            ax += ee * v.x; ay += ee * v.y; az += ee * v.z; aw += ee * v.w;
        }
    }
    float den = denp;
#pragma unroll
    for (int o = 16; o > 0; o >>= 1) den += __shfl_xor_sync(0xffffffffu, den, o);
    const float inv = __fdividef(1.0f, den + 1e-16f);
    const float4 b = *(const float4*)(bias2 + lane * 4);
    const float h0 = fmaxf(ax * inv + b.x, 0.0f);
    const float h1 = fmaxf(ay * inv + b.y, 0.0f);
    const float h2 = fmaxf(az * inv + b.z, 0.0f);
    const float h3 = fmaxf(aw * inv + b.w, 0.0f);
#pragma unroll
    for (int c = 0; c < NCLS; c++) {
        const float4 wv = __ldg((const float4*)(Wfc + c * 128 + lane * 4));
        float p = h0 * wv.x + h1 * wv.y + h2 * wv.z + h3 * wv.w;
#pragma unroll
        for (int o = 16; o > 0; o >>= 1) p += __shfl_xor_sync(0xffffffffu, p, o);
        if (lane == 0) out[(size_t)d * NCLS + c] = p + bfc[c];
    }
}

#define GEMM1_SMEM ((64 * 260 + 64 * 520) * 4)
#define GEMM2_SMEM ((64 * 516 + 64 * 136) * 4)

extern "C" void kernel_launch(void* const* d_in, const int* in_sizes, int n_in,
                              void* d_out, int out_size) {
    const float* x      = (const float*)d_in[0];
    const int*   lens   = (const int*)d_in[1];
    const int*   ei     = (const int*)d_in[2];
    const float* Wih_f  = (const float*)d_in[3];
    const float* Whh_f  = (const float*)d_in[4];
    const float* b_f    = (const float*)d_in[5];
    const float* Wih_b  = (const float*)d_in[6];
    const float* Whh_b  = (const float*)d_in[7];
    const float* b_b    = (const float*)d_in[8];
    const float* W1     = (const float*)d_in[9];
    const float* a1s    = (const float*)d_in[10];
    const float* a1d    = (const float*)d_in[11];
    const float* bias1  = (const float*)d_in[12];
    const float* W2     = (const float*)d_in[13];
    const float* a2s    = (const float*)d_in[14];
    const float* a2d    = (const float*)d_in[15];
    const float* bias2  = (const float*)d_in[16];
    const float* Wfc    = (const float*)d_in[17];
    const float* bfc    = (const float*)d_in[18];
    float* out = (float*)d_out;

    float *p_hcat, *p_xh1, *p_al1s, *p_al1d, *p_agg1, *p_xh2, *p_al2s, *p_al2d;
    float *p_W1t, *p_W2t;
    cudaGetSymbolAddress((void**)&p_hcat, g_hcat);
    cudaGetSymbolAddress((void**)&p_xh1,  g_xh1);
    cudaGetSymbolAddress((void**)&p_al1s, g_al1s);
    cudaGetSymbolAddress((void**)&p_al1d, g_al1d);
    cudaGetSymbolAddress((void**)&p_agg1, g_agg1);
    cudaGetSymbolAddress((void**)&p_xh2,  g_xh2);
    cudaGetSymbolAddress((void**)&p_al2s, g_al2s);
    cudaGetSymbolAddress((void**)&p_al2d, g_al2d);
    cudaGetSymbolAddress((void**)&p_W1t,  g_W1t);
    cudaGetSymbolAddress((void**)&p_W2t,  g_W2t);

    cudaFuncSetAttribute(pre_gemm, cudaFuncAttributeMaxDynamicSharedMemorySize, PRE_SMEM);
    cudaFuncSetAttribute(lstm_rec, cudaFuncAttributeMaxDynamicSharedMemorySize, REC_SMEM);
    cudaFuncSetAttribute(gemm_mma<256, 512>, cudaFuncAttributeMaxDynamicSharedMemorySize, GEMM1_SMEM);
    cudaFuncSetAttribute(gemm_mma<512, 128>, cudaFuncAttributeMaxDynamicSharedMemorySize, GEMM2_SMEM);

    // weight prep + CSR build (independent of LSTM)
    prep_w<<<1024, 256>>>(Wih_f, Whh_f, Wih_b, Whh_b);
    prep_gw<<<(256 * 512 + 512 * 128 + 255) / 256, 256>>>(W1, W2);
    csr_zero<<<(NN + 255) / 256, 256>>>();
    csr_hist<<<(EN + 255) / 256, 256>>>(ei);
    csr_scan<<<1, 1024>>>();
    csr_scatter<<<(EN + 255) / 256, 256>>>(ei);

    // BiLSTM: parallel input projection, then recurrent h-GEMM only
    pre_gemm<<<dim3(NROWS / 64, 2), 512, PRE_SMEM>>>(x);
    lstm_rec<<<dim3((NN + 63) / 64, 2), 512, REC_SMEM>>>(lens, b_f, b_b);

    // GAT layer 1
    gemm_mma<256, 512><<<313, 512, GEMM1_SMEM>>>(p_hcat, p_W1t, p_xh1);
    gat_al<4><<<NN * 4 / 8, 256>>>(p_xh1, a1s, a1d, p_al1s, p_al1d);
    gat_gather4<<<(NN * 4 + 7) / 8, 256>>>(bias1);

    // GAT layer 2
    gemm_mma<512, 128><<<313, 512, GEMM2_SMEM>>>(p_agg1, p_W2t, p_xh2);
    gat_al<1><<<(NN + 7) / 8, 256>>>(p_xh2, a2s, a2d, p_al2s, p_al2d);
    gat_gather1_fc<<<(NN + 7) / 8, 256>>>(bias2, Wfc, bfc, out);
}

// round 12
// speedup vs baseline: 1.3869x; 1.3869x over previous
#include <cuda_runtime.h>
#include <cuda_fp16.h>
#include <math.h>
#include <stdint.h>

#define NN 20000
#define TT 20
#define FF 128
#define HH 128
#define GHD 128
#define NHEADS 4
#define NCLS 10
#define EE 640000
#define EN (EE + NN)

// ---------------- scratch (device globals: allocation-free rule) ----------------
__device__ float g_hcat[NN * 256];
__device__ float g_xh1[NN * 512];
__device__ float g_al1s[NN * 4];
__device__ float g_al1d[NN * 4];
__device__ float g_agg1[NN * 512];
__device__ float g_xh2[NN * 128];
__device__ float g_al2s[NN];
__device__ float g_al2d[NN];
// fp16 weights: LSTM [dir][gatecol=512][k=256] (k<128: Wih, k>=128: Whh)
__device__ __half g_Wth[2 * 512 * 256];
// GAT weights fp16, [col][k] (== torch layout)
__device__ __half g_W1th[512 * 256];
__device__ __half g_W2th[128 * 512];
// CSR by dst
__device__ int g_cnt[NN];
__device__ int g_base[NN + 1];
__device__ int g_srcs[EN];

__device__ __forceinline__ float lrelu(float x) { return x > 0.0f ? x : 0.2f * x; }
__device__ __forceinline__ float fsig(float x) { return __fdividef(1.0f, 1.0f + __expf(-x)); }
__device__ __forceinline__ float ftanh(float x) {
    return __fdividef(2.0f, 1.0f + __expf(-2.0f * x)) - 1.0f;
}
__device__ __forceinline__ uint32_t smem_u32(const void* p) {
    uint32_t a;
    asm("{ .reg .u64 t; cvta.to.shared.u64 t, %1; cvt.u32.u64 %0, t; }" : "=r"(a) : "l"(p));
    return a;
}
#define CP16(dst, src)    asm volatile("cp.async.cg.shared.global [%0], [%1], 16;" :: "r"(dst), "l"(src))
#define CP_COMMIT()       asm volatile("cp.async.commit_group;" ::: "memory")
#define CP_WAIT0()        asm volatile("cp.async.wait_group 0;" ::: "memory")

// m16n8k16 fp16 mma, fp32 accumulate. A row-major, B col-major.
__device__ __forceinline__ void mma_f16(float* d, uint32_t a0, uint32_t a1, uint32_t a2,
                                        uint32_t a3, uint32_t b0, uint32_t b1) {
    asm volatile("mma.sync.aligned.m16n8k16.row.col.f32.f16.f16.f32 "
                 "{%0,%1,%2,%3}, {%4,%5,%6,%7}, {%8,%9}, {%0,%1,%2,%3};"
                 : "+f"(d[0]), "+f"(d[1]), "+f"(d[2]), "+f"(d[3])
                 : "r"(a0), "r"(a1), "r"(a2), "r"(a3), "r"(b0), "r"(b1));
}

// ---------------- weight prep (fp16) ----------------
__global__ void prep_w(const float* __restrict__ Wih_f, const float* __restrict__ Whh_f,
                       const float* __restrict__ Wih_b, const float* __restrict__ Whh_b) {
    const int idx = blockIdx.x * blockDim.x + threadIdx.x;
    if (idx >= 2 * 512 * 256) return;
    const int dir = idx >> 17;
    const int rem = idx & 131071;
    const int c = rem >> 8;        // gate col 0..511
    const int k = rem & 255;       // 0..255
    const float* Ws = dir ? (k < 128 ? Wih_b : Whh_b) : (k < 128 ? Wih_f : Whh_f);
    g_Wth[idx] = __float2half_rn(Ws[(size_t)c * 128 + (k & 127)]);
}
__global__ void prep_gw(const float* __restrict__ W1, const float* __restrict__ W2) {
    const int idx = blockIdx.x * blockDim.x + threadIdx.x;
    if (idx < 512 * 256) g_W1th[idx] = __float2half_rn(W1[idx]);
    const int j = idx - 512 * 256;
    if (j >= 0 && j < 128 * 512) g_W2th[j] = __float2half_rn(W2[j]);
}

// ---------------- CSR build (edges + self loops, grouped by dst) ----------------
__global__ void csr_zero() {
    const int i = blockIdx.x * blockDim.x + threadIdx.x;
    if (i < NN) g_cnt[i] = 0;
}
__global__ void csr_hist(const int* __restrict__ ei) {
    const int e = blockIdx.x * blockDim.x + threadIdx.x;
    if (e >= EN) return;
    const int d = (e < EE) ? ei[EE + e] : (e - EE);
    atomicAdd(&g_cnt[d], 1);
}
__global__ void __launch_bounds__(1024, 1) csr_scan() {
    __shared__ int ps[1024];
    const int tid = threadIdx.x;
    const int base = tid * 20;
    int local[20];
    int s = 0;
#pragma unroll
    for (int i = 0; i < 20; i++) {
        const int idx = base + i;
        const int c = (idx < NN) ? g_cnt[idx] : 0;
        local[i] = s;
        s += c;
    }
    ps[tid] = s;
    __syncthreads();
    for (int off = 1; off < 1024; off <<= 1) {
        int v = (tid >= off) ? ps[tid - off] : 0;
        __syncthreads();
        ps[tid] += v;
        __syncthreads();
    }
    const int excl = (tid == 0) ? 0 : ps[tid - 1];
#pragma unroll
    for (int i = 0; i < 20; i++) {
        const int idx = base + i;
        if (idx < NN) g_base[idx] = excl + local[i];
    }
    if (tid == 1023) g_base[NN] = ps[1023];
    __syncthreads();
    for (int i = tid; i < NN; i += 1024) g_cnt[i] = g_base[i];  // cursor
}
__global__ void csr_scatter(const int* __restrict__ ei) {
    const int e = blockIdx.x * blockDim.x + threadIdx.x;
    if (e >= EN) return;
    int s, d;
    if (e < EE) { s = ei[e]; d = ei[EE + e]; } else { s = d = e - EE; }
    const int pos = atomicAdd(&g_cnt[d], 1);
    g_srcs[pos] = s;
}

// ---------------- BiLSTM via fp16 mma (m16n8k16), 32 seqs/CTA, 2 CTAs/SM ----------------
// A smem: [32 rows][264 halves] (x cols 0-127, h cols 128-255).
// B smem: K=32-chunks, [512 gatecols][40 halves] x2 (cp.async double buffer).
#define SAH 264
#define SBH 40
#define BHOFF 20480            // halves per B buffer (512*40)
#define LSTM_A_B   16896       // bytes: 32*264*2
#define LSTM_BIAS  98816       // 16896 + 2*512*40*2
#define LSTM_LEN   100864
#define LSTM_SMEM  100992

__global__ void __launch_bounds__(256, 2) lstm_mma(
    const float* __restrict__ x, const int* __restrict__ lengths,
    const float* __restrict__ b_f, const float* __restrict__ b_b)
{
    extern __shared__ char smraw[];
    __half* const A_h   = (__half*)smraw;
    __half* const B_h   = (__half*)(smraw + LSTM_A_B);
    float*  const biasf = (float*)(smraw + LSTM_BIAS);
    int*    const len_s = (int*)(smraw + LSTM_LEN);
    const uint32_t B_u = smem_u32(B_h);

    const int tid = threadIdx.x;
    const int wid = tid >> 5, lane = tid & 31;
    const int g = lane >> 2, ctg = lane & 3;
    const int dir = blockIdx.y;
    const int seq0 = blockIdx.x * 32;
    const float* __restrict__ bb = dir ? b_b : b_f;
    const __half* __restrict__ Wt = g_Wth + (size_t)dir * 131072;

    const int rg = wid >> 2, q = wid & 3;
    const int rA = rg * 16 + g, rB = rA + 8;

    biasf[tid] = bb[tid];
    biasf[tid + 256] = bb[tid + 256];
    if (tid < 32) len_s[tid] = lengths[seq0 + tid];
    for (int i = tid; i < 32 * 64; i += 256) {       // zero h region (u32 = 2 halves)
        const int row = i >> 6, c = i & 63;
        *(uint32_t*)(A_h + row * SAH + 128 + c * 2) = 0;
    }
    __syncthreads();

    const int lenA = len_s[rA], lenB = len_s[rB];

    float acc[4][4][4];   // [gate][ntile][frag]
    float cst[4][4];
#pragma unroll
    for (int ni = 0; ni < 4; ni++)
#pragma unroll
        for (int p = 0; p < 4; p++) cst[ni][p] = 0.0f;

    for (int t = 0; t < TT; t++) {
        // stage x_t (fp16-rounded) into A cols 0..127
#pragma unroll
        for (int j = 0; j < 4; j++) {
            const int idx = j * 256 + tid;
            const int row = idx >> 5, f4 = idx & 31;
            const int ls = len_s[row];
            const int ttv = dir ? max(ls - 1 - t, 0) : t;
            const float4 v = *(const float4*)(x + ((size_t)(seq0 + row) * TT + ttv) * FF + f4 * 4);
            *(__half2*)(A_h + row * SAH + f4 * 4)     = __floats2half2_rn(v.x, v.y);
            *(__half2*)(A_h + row * SAH + f4 * 4 + 2) = __floats2half2_rn(v.z, v.w);
        }
#pragma unroll
        for (int gi = 0; gi < 4; gi++)
#pragma unroll
            for (int ni = 0; ni < 4; ni++)
#pragma unroll
                for (int p = 0; p < 4; p++) acc[gi][ni][p] = 0.0f;

        // prefetch B chunk 0 (512 rows x 32 halves = 64B/row, 4 CP16s/row)
#pragma unroll
        for (int j = 0; j < 8; j++) {
            const int idx = j * 256 + tid;
            const int row = idx >> 2, part = idx & 3;
            CP16(B_u + (row * SBH + part * 8) * 2, Wt + row * 256 + part * 8);
        }
        CP_COMMIT();

        for (int kc = 0; kc < 8; kc++) {
            CP_WAIT0();
            __syncthreads();
            if (kc < 7) {
                const int nb = (kc + 1) & 1;
                const __half* src = Wt + (kc + 1) * 32;
#pragma unroll
                for (int j = 0; j < 8; j++) {
                    const int idx = j * 256 + tid;
                    const int row = idx >> 2, part = idx & 3;
                    CP16(B_u + (nb * BHOFF + row * SBH + part * 8) * 2,
                         src + row * 256 + part * 8);
                }
                CP_COMMIT();
            }
            const __half* Bb = B_h + (kc & 1) * BHOFF;
#pragma unroll
            for (int ks = 0; ks < 2; ks++) {
                const int kA = kc * 32 + ks * 16;
                const uint32_t a0 = *(const uint32_t*)(A_h + rA * SAH + kA + 2 * ctg);
                const uint32_t a1 = *(const uint32_t*)(A_h + rB * SAH + kA + 2 * ctg);
                const uint32_t a2 = *(const uint32_t*)(A_h + rA * SAH + kA + 8 + 2 * ctg);
                const uint32_t a3 = *(const uint32_t*)(A_h + rB * SAH + kA + 8 + 2 * ctg);
#pragma unroll
                for (int gi = 0; gi < 4; gi++) {
#pragma unroll
                    for (int ni = 0; ni < 4; ni++) {
                        const int n0 = gi * 128 + q * 32 + ni * 8;
                        const __half* bp = Bb + (n0 + g) * SBH + ks * 16 + 2 * ctg;
                        const uint32_t b0 = *(const uint32_t*)bp;
                        const uint32_t b1 = *(const uint32_t*)(bp + 8);
                        mma_f16(acc[gi][ni], a0, a1, a2, a3, b0, b1);
                    }
                }
            }
        }

        __syncthreads();   // all mma reads of A_h done before h writeback

        // cell math (register-local), h writeback (fp16)
#pragma unroll
        for (int ni = 0; ni < 4; ni++) {
            const int hc0 = q * 32 + ni * 8 + 2 * ctg;
#pragma unroll
            for (int p = 0; p < 4; p++) {
                const int col = hc0 + (p & 1);
                const int row = (p < 2) ? rA : rB;
                const bool act = t < ((p < 2) ? lenA : lenB);
                const float pi = acc[0][ni][p] + biasf[col];
                const float pf = acc[1][ni][p] + biasf[128 + col];
                const float pg = acc[2][ni][p] + biasf[256 + col];
                const float po = acc[3][ni][p] + biasf[384 + col];
                const float cn = fsig(pf) * cst[ni][p] + fsig(pi) * ftanh(pg);
                const float hn = fsig(po) * ftanh(cn);
                if (act) {
                    cst[ni][p] = cn;
                    A_h[row * SAH + 128 + col] = __float2half_rn(hn);
                }
            }
        }
        __syncthreads();
    }

    // final frozen h -> g_hcat (fp32)
    for (int i = tid; i < 32 * 32; i += 256) {
        const int row = i >> 5, c4 = i & 31;
        const __half* hp = A_h + row * SAH + 128 + c4 * 4;
        float4 o;
        o.x = __half2float(hp[0]); o.y = __half2float(hp[1]);
        o.z = __half2float(hp[2]); o.w = __half2float(hp[3]);
        *(float4*)(g_hcat + (size_t)(seq0 + row) * 256 + dir * 128 + c4 * 4) = o;
    }
}

// ---------------- generic fp16 tensor GEMM: C[N][COLS] = A[N][KTOT] @ W[COLS][KTOT]^T ----
// 64 rows/CTA, 512 threads. B global layout [COLS][KTOT] half.
template <int KTOT, int COLS>
__global__ void __launch_bounds__(512, 1) gemm_mma(
    const float* __restrict__ A, const __half* __restrict__ Bt, float* __restrict__ C)
{
    constexpr int SAH2 = KTOT + 8;
    constexpr int GI = COLS / 128;
    constexpr int BHALF = COLS * SBH;
    extern __shared__ char smraw[];
    __half* const A_h = (__half*)smraw;
    __half* const B_h = (__half*)(smraw + 64 * SAH2 * 2);
    const uint32_t B_u = smem_u32(B_h);

    const int tid = threadIdx.x;
    const int wid = tid >> 5, lane = tid & 31;
    const int g = lane >> 2, ctg = lane & 3;
    const int rg = wid >> 2, q = wid & 3;
    const int rA = rg * 16 + g, rB = rA + 8;
    const int row0 = blockIdx.x * 64;

    constexpr int K4 = KTOT / 4;
    for (int idx = tid; idx < 64 * K4; idx += 512) {
        const int row = idx / K4, c4 = idx % K4;
        const int sq = min(row0 + row, NN - 1);
        const float4 v = *(const float4*)(A + (size_t)sq * KTOT + c4 * 4);
        *(__half2*)(A_h + row * SAH2 + c4 * 4)     = __floats2half2_rn(v.x, v.y);
        *(__half2*)(A_h + row * SAH2 + c4 * 4 + 2) = __floats2half2_rn(v.z, v.w);
    }

    float acc[GI][4][4];
#pragma unroll
    for (int gi = 0; gi < GI; gi++)
#pragma unroll
        for (int ni = 0; ni < 4; ni++)
#pragma unroll
            for (int p = 0; p < 4; p++) acc[gi][ni][p] = 0.0f;

    constexpr int NC = KTOT / 32;
    // prefetch chunk 0: COLS rows x 64B
    for (int j = tid; j < COLS * 4; j += 512) {
        const int row = j >> 2, part = j & 3;
        CP16(B_u + (row * SBH + part * 8) * 2, Bt + (size_t)row * KTOT + part * 8);
    }
    CP_COMMIT();

    for (int kc = 0; kc < NC; kc++) {
        CP_WAIT0();
        __syncthreads();
        if (kc < NC - 1) {
            const int nb = (kc + 1) & 1;
            const __half* src = Bt + (kc + 1) * 32;
            for (int j = tid; j < COLS * 4; j += 512) {
                const int row = j >> 2, part = j & 3;
                CP16(B_u + (nb * BHALF + row * SBH + part * 8) * 2,
                     src + (size_t)row * KTOT + part * 8);
            }
            CP_COMMIT();
        }
        const __half* Bb = B_h + (kc & 1) * BHALF;
#pragma unroll
        for (int ks = 0; ks < 2; ks++) {
            const int kA = kc * 32 + ks * 16;
            const uint32_t a0 = *(const uint32_t*)(A_h + rA * SAH2 + kA + 2 * ctg);
            const uint32_t a1 = *(const uint32_t*)(A_h + rB * SAH2 + kA + 2 * ctg);
            const uint32_t a2 = *(const uint32_t*)(A_h + rA * SAH2 + kA + 8 + 2 * ctg);
            const uint32_t a3 = *(const uint32_t*)(A_h + rB * SAH2 + kA + 8 + 2 * ctg);
#pragma unroll
            for (int gi = 0; gi < GI; gi++) {
#pragma unroll
                for (int ni = 0; ni < 4; ni++) {
                    const int n0 = gi * 128 + q * 32 + ni * 8;
                    const __half* bp = Bb + (n0 + g) * SBH + ks * 16 + 2 * ctg;
                    const uint32_t b0 = *(const uint32_t*)bp;
                    const uint32_t b1 = *(const uint32_t*)(bp + 8);
                    mma_f16(acc[gi][ni], a0, a1, a2, a3, b0, b1);
                }
            }
        }
    }

#pragma unroll
    for (int gi = 0; gi < GI; gi++)
#pragma unroll
        for (int ni = 0; ni < 4; ni++) {
            const int n0 = gi * 128 + q * 32 + ni * 8 + 2 * ctg;
            if (row0 + rA < NN)
                *(float2*)(C + (size_t)(row0 + rA) * COLS + n0) =
                    make_float2(acc[gi][ni][0], acc[gi][ni][1]);
            if (row0 + rB < NN)
                *(float2*)(C + (size_t)(row0 + rB) * COLS + n0) =
                    make_float2(acc[gi][ni][2], acc[gi][ni][3]);
        }
}

// ---------------- GAT attention-logit projections (warp per (node, head)) ----------------
template <int NH>
__global__ void gat_al(const float* __restrict__ xh, const float* __restrict__ asrc,
                       const float* __restrict__ adst, float* __restrict__ als,
                       float* __restrict__ ald)
{
    const int w = (blockIdx.x * blockDim.x + threadIdx.x) >> 5;
    const int lane = threadIdx.x & 31;
    if (w >= NN * NH) return;
    const int n = w / NH, h = w % NH;
    const float4 v  = *(const float4*)(xh + (size_t)n * (NH * GHD) + h * GHD + lane * 4);
    const float4 s4 = *(const float4*)(asrc + h * GHD + lane * 4);
    const float4 d4 = *(const float4*)(adst + h * GHD + lane * 4);
    float s = v.x * s4.x + v.y * s4.y + v.z * s4.z + v.w * s4.w;
    float d = v.x * d4.x + v.y * d4.y + v.z * d4.z + v.w * d4.w;
#pragma unroll
    for (int o = 16; o > 0; o >>= 1) {
        s += __shfl_xor_sync(0xffffffffu, s, o);
        d += __shfl_xor_sync(0xffffffffu, d, o);
    }
    if (lane == 0) { als[w] = s; ald[w] = d; }
}

// ---------------- layer-1 gather: warp per (dst, head), lane-parallel edge prologue ------
__global__ void gat_gather4(const float* __restrict__ bias1) {
    const int w = (blockIdx.x * blockDim.x + threadIdx.x) >> 5;
    const int lane = threadIdx.x & 31;
    if (w >= NN * NHEADS) return;
    const int d = w >> 2, h = w & 3;
    const float aldv = g_al1d[d * 4 + h];
    const int beg = g_base[d], end = g_base[d + 1];
    float ax = 0.0f, ay = 0.0f, az = 0.0f, aw = 0.0f, denp = 0.0f;
    for (int eb = beg; eb < end; eb += 32) {
        const int ne = end - eb;
        int sl = 0; float eel = 0.0f;
        if (lane < ne) {
            sl = g_srcs[eb + lane];
            eel = __expf(lrelu(g_al1s[sl * 4 + h] + aldv));
        }
        denp += eel;
        const int m = min(ne, 32);
#pragma unroll 4
        for (int j = 0; j < m; j++) {
            const int s = __shfl_sync(0xffffffffu, sl, j);
            const float ee = __shfl_sync(0xffffffffu, eel, j);
            const float4 v = *(const float4*)(g_xh1 + (size_t)s * 512 + h * GHD + lane * 4);
            ax += ee * v.x; ay += ee * v.y; az += ee * v.z; aw += ee * v.w;
        }
    }
    float den = denp;
#pragma unroll
    for (int o = 16; o > 0; o >>= 1) den += __shfl_xor_sync(0xffffffffu, den, o);
    const float inv = __fdividef(1.0f, den + 1e-16f);
    const float4 b = *(const float4*)(bias1 + h * GHD + lane * 4);
    float4 o;
    o.x = fmaxf(ax * inv + b.x, 0.0f);
    o.y = fmaxf(ay * inv + b.y, 0.0f);
    o.z = fmaxf(az * inv + b.z, 0.0f);
    o.w = fmaxf(aw * inv + b.w, 0.0f);
    *(float4*)(g_agg1 + (size_t)d * 512 + h * GHD + lane * 4) = o;
}

// ---------------- layer-2 gather + fused FC: warp per dst ----------------
__global__ void gat_gather1_fc(const float* __restrict__ bias2,
                               const float* __restrict__ Wfc, const float* __restrict__ bfc,
                               float* __restrict__ out) {
    const int w = (blockIdx.x * blockDim.x + threadIdx.x) >> 5;
    const int lane = threadIdx.x & 31;
    if (w >= NN) return;
    const int d = w;
    const float aldv = g_al2d[d];
    const int beg = g_base[d], end = g_base[d + 1];
    float ax = 0.0f, ay = 0.0f, az = 0.0f, aw = 0.0f, denp = 0.0f;
    for (int eb = beg; eb < end; eb += 32) {
        const int ne = end - eb;
        int sl = 0; float eel = 0.0f;
        if (lane < ne) {
            sl = g_srcs[eb + lane];
            eel = __expf(lrelu(g_al2s[sl] + aldv));
        }
        denp += eel;
        const int m = min(ne, 32);
#pragma unroll 4
        for (int j = 0; j < m; j++) {
            const int s = __shfl_sync(0xffffffffu, sl, j);
            const float ee = __shfl_sync(0xffffffffu, eel, j);
            const float4 v = *(const float4*)(g_xh2 + (size_t)s * 128 + lane * 4);
            ax += ee * v.x; ay += ee * v.y; az += ee * v.z; aw += ee * v.w;
        }
    }
    float den = denp;
#pragma unroll
    for (int o = 16; o > 0; o >>= 1) den += __shfl_xor_sync(0xffffffffu, den, o);
    const float inv = __fdividef(1.0f, den + 1e-16f);
    const float4 b = *(const float4*)(bias2 + lane * 4);
    const float h0 = fmaxf(ax * inv + b.x, 0.0f);
    const float h1 = fmaxf(ay * inv + b.y, 0.0f);
    const float h2 = fmaxf(az * inv + b.z, 0.0f);
    const float h3 = fmaxf(aw * inv + b.w, 0.0f);
#pragma unroll
    for (int c = 0; c < NCLS; c++) {
        const float4 wv = __ldg((const float4*)(Wfc + c * 128 + lane * 4));
        float p = h0 * wv.x + h1 * wv.y + h2 * wv.z + h3 * wv.w;
#pragma unroll
        for (int o = 16; o > 0; o >>= 1) p += __shfl_xor_sync(0xffffffffu, p, o);
        if (lane == 0) out[(size_t)d * NCLS + c] = p + bfc[c];
    }
}

#define GEMM1_SMEM ((64 * 264 + 2 * 512 * SBH) * 2)
#define GEMM2_SMEM ((64 * 520 + 2 * 128 * SBH) * 2)

extern "C" void kernel_launch(void* const* d_in, const int* in_sizes, int n_in,
                              void* d_out, int out_size) {
    const float* x      = (const float*)d_in[0];
    const int*   lens   = (const int*)d_in[1];
    const int*   ei     = (const int*)d_in[2];
    const float* Wih_f  = (const float*)d_in[3];
    const float* Whh_f  = (const float*)d_in[4];
    const float* b_f    = (const float*)d_in[5];
    const float* Wih_b  = (const float*)d_in[6];
    const float* Whh_b  = (const float*)d_in[7];
    const float* b_b    = (const float*)d_in[8];
    const float* W1     = (const float*)d_in[9];
    const float* a1s    = (const float*)d_in[10];
    const float* a1d    = (const float*)d_in[11];
    const float* bias1  = (const float*)d_in[12];
    const float* W2     = (const float*)d_in[13];
    const float* a2s    = (const float*)d_in[14];
    const float* a2d    = (const float*)d_in[15];
    const float* bias2  = (const float*)d_in[16];
    const float* Wfc    = (const float*)d_in[17];
    const float* bfc    = (const float*)d_in[18];
    float* out = (float*)d_out;

    float *p_hcat, *p_xh1, *p_al1s, *p_al1d, *p_agg1, *p_xh2, *p_al2s, *p_al2d;
    __half *p_W1th, *p_W2th;
    cudaGetSymbolAddress((void**)&p_hcat, g_hcat);
    cudaGetSymbolAddress((void**)&p_xh1,  g_xh1);
    cudaGetSymbolAddress((void**)&p_al1s, g_al1s);
    cudaGetSymbolAddress((void**)&p_al1d, g_al1d);
    cudaGetSymbolAddress((void**)&p_agg1, g_agg1);
    cudaGetSymbolAddress((void**)&p_xh2,  g_xh2);
    cudaGetSymbolAddress((void**)&p_al2s, g_al2s);
    cudaGetSymbolAddress((void**)&p_al2d, g_al2d);
    cudaGetSymbolAddress((void**)&p_W1th, g_W1th);
    cudaGetSymbolAddress((void**)&p_W2th, g_W2th);

    cudaFuncSetAttribute(lstm_mma, cudaFuncAttributeMaxDynamicSharedMemorySize, LSTM_SMEM);
    cudaFuncSetAttribute(gemm_mma<256, 512>, cudaFuncAttributeMaxDynamicSharedMemorySize, GEMM1_SMEM);
    cudaFuncSetAttribute(gemm_mma<512, 128>, cudaFuncAttributeMaxDynamicSharedMemorySize, GEMM2_SMEM);

    // weight prep + CSR build (independent of LSTM)
    prep_w<<<1024, 256>>>(Wih_f, Whh_f, Wih_b, Whh_b);
    prep_gw<<<(512 * 256 + 128 * 512 + 255) / 256, 256>>>(W1, W2);
    csr_zero<<<(NN + 255) / 256, 256>>>();
    csr_hist<<<(EN + 255) / 256, 256>>>(ei);
    csr_scan<<<1, 1024>>>();
    csr_scatter<<<(EN + 255) / 256, 256>>>(ei);

    // BiLSTM (fp16 tensor path)
    lstm_mma<<<dim3(625, 2), 256, LSTM_SMEM>>>(x, lens, b_f, b_b);

    // GAT layer 1
    gemm_mma<256, 512><<<313, 512, GEMM1_SMEM>>>(p_hcat, p_W1th, p_xh1);
    gat_al<4><<<NN * 4 / 8, 256>>>(p_xh1, a1s, a1d, p_al1s, p_al1d);
    gat_gather4<<<(NN * 4 + 7) / 8, 256>>>(bias1);

    // GAT layer 2
    gemm_mma<512, 128><<<313, 512, GEMM2_SMEM>>>(p_agg1, p_W2th, p_xh2);
    gat_al<1><<<(NN + 7) / 8, 256>>>(p_xh2, a2s, a2d, p_al2s, p_al2d);
    gat_gather1_fc<<<(NN + 7) / 8, 256>>>(bias2, Wfc, bfc, out);
}

// round 17
// speedup vs baseline: 1.6268x; 1.1729x over previous
#include <cuda_runtime.h>
#include <cuda_fp16.h>
#include <math.h>
#include <stdint.h>

#define NN 20000
#define TT 20
#define FF 128
#define HH 128
#define GHD 128
#define NHEADS 4
#define NCLS 10
#define EE 640000
#define EN (EE + NN)

// ---------------- scratch (device globals: allocation-free rule) ----------------
__device__ float g_hcat[NN * 256];
__device__ float g_xh1[NN * 512];
__device__ float g_al1s[NN * 4];
__device__ float g_al1d[NN * 4];
__device__ float g_agg1[NN * 512];
__device__ float g_xh2[NN * 128];
__device__ float g_al2s[NN];
__device__ float g_al2d[NN];
// fp16 weights: LSTM [dir][gatecol=512][k=256] (k<128: Wih, k>=128: Whh)
__device__ __half g_Wth[2 * 512 * 256];
// GAT weights fp16, [col][k] (== torch layout)
__device__ __half g_W1th[512 * 256];
__device__ __half g_W2th[128 * 512];
// CSR by dst
__device__ int g_cnt[NN];
__device__ int g_base[NN + 1];
__device__ int g_srcs[EN];

__device__ __forceinline__ float lrelu(float x) { return x > 0.0f ? x : 0.2f * x; }
__device__ __forceinline__ float fsig(float x) { return __fdividef(1.0f, 1.0f + __expf(-x)); }
__device__ __forceinline__ float ftanh(float x) {
    return __fdividef(2.0f, 1.0f + __expf(-2.0f * x)) - 1.0f;
}
__device__ __forceinline__ uint32_t smem_u32(const void* p) {
    uint32_t a;
    asm("{ .reg .u64 t; cvta.to.shared.u64 t, %1; cvt.u32.u64 %0, t; }" : "=r"(a) : "l"(p));
    return a;
}
#define CP16(dst, src)    asm volatile("cp.async.cg.shared.global [%0], [%1], 16;" :: "r"(dst), "l"(src))
#define CP_COMMIT()       asm volatile("cp.async.commit_group;" ::: "memory")
#define CP_WAIT0()        asm volatile("cp.async.wait_group 0;" ::: "memory")

// m16n8k16 fp16 mma, fp32 accumulate. A row-major, B col-major.
__device__ __forceinline__ void mma_f16(float* d, uint32_t a0, uint32_t a1, uint32_t a2,
                                        uint32_t a3, uint32_t b0, uint32_t b1) {
    asm volatile("mma.sync.aligned.m16n8k16.row.col.f32.f16.f16.f32 "
                 "{%0,%1,%2,%3}, {%4,%5,%6,%7}, {%8,%9}, {%0,%1,%2,%3};"
                 : "+f"(d[0]), "+f"(d[1]), "+f"(d[2]), "+f"(d[3])
                 : "r"(a0), "r"(a1), "r"(a2), "r"(a3), "r"(b0), "r"(b1));
}
#define LDSM_X4(r0, r1, r2, r3, addr)                                          \
    asm volatile("ldmatrix.sync.aligned.m8n8.x4.shared.b16 {%0,%1,%2,%3}, [%4];" \
                 : "=r"(r0), "=r"(r1), "=r"(r2), "=r"(r3) : "r"(addr))

// ---------------- weight prep (fp16) ----------------
__global__ void prep_w(const float* __restrict__ Wih_f, const float* __restrict__ Whh_f,
                       const float* __restrict__ Wih_b, const float* __restrict__ Whh_b) {
    const int idx = blockIdx.x * blockDim.x + threadIdx.x;
    if (idx >= 2 * 512 * 256) return;
    const int dir = idx >> 17;
    const int rem = idx & 131071;
    const int c = rem >> 8;        // gate col 0..511
    const int k = rem & 255;       // 0..255
    const float* Ws = dir ? (k < 128 ? Wih_b : Whh_b) : (k < 128 ? Wih_f : Whh_f);
    g_Wth[idx] = __float2half_rn(Ws[(size_t)c * 128 + (k & 127)]);
}
__global__ void prep_gw(const float* __restrict__ W1, const float* __restrict__ W2) {
    const int idx = blockIdx.x * blockDim.x + threadIdx.x;
    if (idx < 512 * 256) g_W1th[idx] = __float2half_rn(W1[idx]);
    const int j = idx - 512 * 256;
    if (j >= 0 && j < 128 * 512) g_W2th[j] = __float2half_rn(W2[j]);
}

// ---------------- CSR build (edges + self loops, grouped by dst) ----------------
__global__ void csr_zero() {
    const int i = blockIdx.x * blockDim.x + threadIdx.x;
    if (i < NN) g_cnt[i] = 0;
}
__global__ void csr_hist(const int* __restrict__ ei) {
    const int e = blockIdx.x * blockDim.x + threadIdx.x;
    if (e >= EN) return;
    const int d = (e < EE) ? ei[EE + e] : (e - EE);
    atomicAdd(&g_cnt[d], 1);
}
__global__ void __launch_bounds__(1024, 1) csr_scan() {
    __shared__ int ps[1024];
    const int tid = threadIdx.x;
    const int base = tid * 20;
    int local[20];
    int s = 0;
#pragma unroll
    for (int i = 0; i < 20; i++) {
        const int idx = base + i;
        const int c = (idx < NN) ? g_cnt[idx] : 0;
        local[i] = s;
        s += c;
    }
    ps[tid] = s;
    __syncthreads();
    for (int off = 1; off < 1024; off <<= 1) {
        int v = (tid >= off) ? ps[tid - off] : 0;
        __syncthreads();
        ps[tid] += v;
        __syncthreads();
    }
    const int excl = (tid == 0) ? 0 : ps[tid - 1];
#pragma unroll
    for (int i = 0; i < 20; i++) {
        const int idx = base + i;
        if (idx < NN) g_base[idx] = excl + local[i];
    }
    if (tid == 1023) g_base[NN] = ps[1023];
    __syncthreads();
    for (int i = tid; i < NN; i += 1024) g_cnt[i] = g_base[i];  // cursor
}
__global__ void csr_scatter(const int* __restrict__ ei) {
    const int e = blockIdx.x * blockDim.x + threadIdx.x;
    if (e >= EN) return;
    int s, d;
    if (e < EE) { s = ei[e]; d = ei[EE + e]; } else { s = d = e - EE; }
    const int pos = atomicAdd(&g_cnt[d], 1);
    g_srcs[pos] = s;
}

// ---------------- BiLSTM via fp16 mma (m16n8k16) + ldmatrix, 32 seqs/CTA, 2 CTAs/SM ------
// A smem: [32 rows][264 halves] (x cols 0-127, h cols 128-255).
// B smem: K=32-chunks, [512 gatecols][40 halves] x2 (cp.async double buffer).
#define SAH 264
#define SBH 40
#define BHOFF 20480            // halves per B buffer (512*40)
#define LSTM_A_B   16896       // bytes: 32*264*2
#define LSTM_BIAS  98816       // 16896 + 2*512*40*2
#define LSTM_LEN   100864
#define LSTM_SMEM  100992

__global__ void __launch_bounds__(256, 2) lstm_mma(
    const float* __restrict__ x, const int* __restrict__ lengths,
    const float* __restrict__ b_f, const float* __restrict__ b_b)
{
    extern __shared__ char smraw[];
    __half* const A_h   = (__half*)smraw;
    __half* const B_h   = (__half*)(smraw + LSTM_A_B);
    float*  const biasf = (float*)(smraw + LSTM_BIAS);
    int*    const len_s = (int*)(smraw + LSTM_LEN);
    const uint32_t B_u = smem_u32(B_h);
    const uint32_t A_u = smem_u32(A_h);

    const int tid = threadIdx.x;
    const int wid = tid >> 5, lane = tid & 31;
    const int g = lane >> 2, ctg = lane & 3;
    const int dir = blockIdx.y;
    const int seq0 = blockIdx.x * 32;
    const float* __restrict__ bb = dir ? b_b : b_f;
    const __half* __restrict__ Wt = g_Wth + (size_t)dir * 131072;

    const int rg = wid >> 2, q = wid & 3;
    const int rA = rg * 16 + g, rB = rA + 8;

    // ldmatrix lane addressing (byte offsets into smem)
    // A x4: matrices (rows0-7,k0-7),(rows8-15,k0-7),(rows0-7,k8-15),(rows8-15,k8-15)
    const uint32_t aBase = A_u +
        (((rg * 16 + (lane & 15)) * SAH) + ((lane >> 4) << 3)) * 2;
    // B x4: matrices (nt0,k0-7),(nt0,k8-15),(nt1,k0-7),(nt1,k8-15)
    const uint32_t bLane = ((q * 32 + ((lane >> 4) << 3) + (lane & 7)) * SBH +
                            (((lane >> 3) & 1) << 3)) * 2;

    biasf[tid] = bb[tid];
    biasf[tid + 256] = bb[tid + 256];
    if (tid < 32) len_s[tid] = lengths[seq0 + tid];
    for (int i = tid; i < 32 * 64; i += 256) {       // zero h region
        const int row = i >> 6, c = i & 63;
        *(uint32_t*)(A_h + row * SAH + 128 + c * 2) = 0;
    }
    __syncthreads();

    const int lenA = len_s[rA], lenB = len_s[rB];

    float acc[4][4][4];   // [gate][ntile][frag]
    float cst[4][4];
#pragma unroll
    for (int ni = 0; ni < 4; ni++)
#pragma unroll
        for (int p = 0; p < 4; p++) cst[ni][p] = 0.0f;

    for (int t = 0; t < TT; t++) {
        // stage x_t (fp16-rounded) into A cols 0..127
#pragma unroll
        for (int j = 0; j < 4; j++) {
            const int idx = j * 256 + tid;
            const int row = idx >> 5, f4 = idx & 31;
            const int ls = len_s[row];
            const int ttv = dir ? max(ls - 1 - t, 0) : t;
            const float4 v = *(const float4*)(x + ((size_t)(seq0 + row) * TT + ttv) * FF + f4 * 4);
            *(__half2*)(A_h + row * SAH + f4 * 4)     = __floats2half2_rn(v.x, v.y);
            *(__half2*)(A_h + row * SAH + f4 * 4 + 2) = __floats2half2_rn(v.z, v.w);
        }
#pragma unroll
        for (int gi = 0; gi < 4; gi++)
#pragma unroll
            for (int ni = 0; ni < 4; ni++)
#pragma unroll
                for (int p = 0; p < 4; p++) acc[gi][ni][p] = 0.0f;

        // prefetch B chunk 0 (512 rows x 32 halves = 64B/row)
#pragma unroll
        for (int j = 0; j < 8; j++) {
            const int idx = j * 256 + tid;
            const int row = idx >> 2, part = idx & 3;
            CP16(B_u + (row * SBH + part * 8) * 2, Wt + row * 256 + part * 8);
        }
        CP_COMMIT();

        for (int kc = 0; kc < 8; kc++) {
            CP_WAIT0();
            __syncthreads();
            if (kc < 7) {
                const int nb = (kc + 1) & 1;
                const __half* src = Wt + (kc + 1) * 32;
#pragma unroll
                for (int j = 0; j < 8; j++) {
                    const int idx = j * 256 + tid;
                    const int row = idx >> 2, part = idx & 3;
                    CP16(B_u + (nb * BHOFF + row * SBH + part * 8) * 2,
                         src + row * 256 + part * 8);
                }
                CP_COMMIT();
            }
            const uint32_t bufB = B_u + (kc & 1) * (BHOFF * 2) + bLane;
#pragma unroll
            for (int ks = 0; ks < 2; ks++) {
                uint32_t a0, a1, a2, a3;
                LDSM_X4(a0, a1, a2, a3, aBase + (kc * 32 + ks * 16) * 2);
#pragma unroll
                for (int gi = 0; gi < 4; gi++) {
#pragma unroll
                    for (int pr = 0; pr < 2; pr++) {
                        uint32_t b0, b1, b2, b3;
                        LDSM_X4(b0, b1, b2, b3,
                                bufB + (((gi * 128 + pr * 16) * SBH) + ks * 16) * 2);
                        mma_f16(acc[gi][pr * 2],     a0, a1, a2, a3, b0, b1);
                        mma_f16(acc[gi][pr * 2 + 1], a0, a1, a2, a3, b2, b3);
                    }
                }
            }
        }

        __syncthreads();   // all mma reads of A_h done before h writeback

        // cell math (register-local), h writeback (fp16)
#pragma unroll
        for (int ni = 0; ni < 4; ni++) {
            const int hc0 = q * 32 + ni * 8 + 2 * ctg;
#pragma unroll
            for (int p = 0; p < 4; p++) {
                const int col = hc0 + (p & 1);
                const int row = (p < 2) ? rA : rB;
                const bool act = t < ((p < 2) ? lenA : lenB);
                const float pi = acc[0][ni][p] + biasf[col];
                const float pf = acc[1][ni][p] + biasf[128 + col];
                const float pg = acc[2][ni][p] + biasf[256 + col];
                const float po = acc[3][ni][p] + biasf[384 + col];
                const float cn = fsig(pf) * cst[ni][p] + fsig(pi) * ftanh(pg);
                const float hn = fsig(po) * ftanh(cn);
                if (act) {
                    cst[ni][p] = cn;
                    A_h[row * SAH + 128 + col] = __float2half_rn(hn);
                }
            }
        }
        __syncthreads();
    }

    // final frozen h -> g_hcat (fp32)
    for (int i = tid; i < 32 * 32; i += 256) {
        const int row = i >> 5, c4 = i & 31;
        const __half* hp = A_h + row * SAH + 128 + c4 * 4;
        float4 o;
        o.x = __half2float(hp[0]); o.y = __half2float(hp[1]);
        o.z = __half2float(hp[2]); o.w = __half2float(hp[3]);
        *(float4*)(g_hcat + (size_t)(seq0 + row) * 256 + dir * 128 + c4 * 4) = o;
    }
}

// ---------------- generic fp16 tensor GEMM: C[N][COLS] = A[N][KTOT] @ W[COLS][KTOT]^T ----
template <int KTOT, int COLS>
__global__ void __launch_bounds__(512, 1) gemm_mma(
    const float* __restrict__ A, const __half* __restrict__ Bt, float* __restrict__ C)
{
    constexpr int SAH2 = KTOT + 8;
    constexpr int GI = COLS / 128;
    constexpr int BHALF = COLS * SBH;
    extern __shared__ char smraw[];
    __half* const A_h = (__half*)smraw;
    __half* const B_h = (__half*)(smraw + 64 * SAH2 * 2);
    const uint32_t B_u = smem_u32(B_h);
    const uint32_t A_u = smem_u32(A_h);

    const int tid = threadIdx.x;
    const int wid = tid >> 5, lane = tid & 31;
    const int g = lane >> 2, ctg = lane & 3;
    const int rg = wid >> 2, q = wid & 3;
    const int rA = rg * 16 + g, rB = rA + 8;
    const int row0 = blockIdx.x * 64;

    const uint32_t aBase = A_u +
        (((rg * 16 + (lane & 15)) * SAH2) + ((lane >> 4) << 3)) * 2;
    const uint32_t bLane = ((q * 32 + ((lane >> 4) << 3) + (lane & 7)) * SBH +
                            (((lane >> 3) & 1) << 3)) * 2;

    constexpr int K4 = KTOT / 4;
    for (int idx = tid; idx < 64 * K4; idx += 512) {
        const int row = idx / K4, c4 = idx % K4;
        const int sq = min(row0 + row, NN - 1);
        const float4 v = *(const float4*)(A + (size_t)sq * KTOT + c4 * 4);
        *(__half2*)(A_h + row * SAH2 + c4 * 4)     = __floats2half2_rn(v.x, v.y);
        *(__half2*)(A_h + row * SAH2 + c4 * 4 + 2) = __floats2half2_rn(v.z, v.w);
    }

    float acc[GI][4][4];
#pragma unroll
    for (int gi = 0; gi < GI; gi++)
#pragma unroll
        for (int ni = 0; ni < 4; ni++)
#pragma unroll
            for (int p = 0; p < 4; p++) acc[gi][ni][p] = 0.0f;

    constexpr int NC = KTOT / 32;
    for (int j = tid; j < COLS * 4; j += 512) {
        const int row = j >> 2, part = j & 3;
        CP16(B_u + (row * SBH + part * 8) * 2, Bt + (size_t)row * KTOT + part * 8);
    }
    CP_COMMIT();

    for (int kc = 0; kc < NC; kc++) {
        CP_WAIT0();
        __syncthreads();
        if (kc < NC - 1) {
            const int nb = (kc + 1) & 1;
            const __half* src = Bt + (kc + 1) * 32;
            for (int j = tid; j < COLS * 4; j += 512) {
                const int row = j >> 2, part = j & 3;
                CP16(B_u + (nb * BHALF + row * SBH + part * 8) * 2,
                     src + (size_t)row * KTOT + part * 8);
            }
            CP_COMMIT();
        }
        const uint32_t bufB = B_u + (kc & 1) * (BHALF * 2) + bLane;
#pragma unroll
        for (int ks = 0; ks < 2; ks++) {
            uint32_t a0, a1, a2, a3;
            LDSM_X4(a0, a1, a2, a3, aBase + (kc * 32 + ks * 16) * 2);
#pragma unroll
            for (int gi = 0; gi < GI; gi++) {
#pragma unroll
                for (int pr = 0; pr < 2; pr++) {
                    uint32_t b0, b1, b2, b3;
                    LDSM_X4(b0, b1, b2, b3,
                            bufB + (((gi * 128 + pr * 16) * SBH) + ks * 16) * 2);
                    mma_f16(acc[gi][pr * 2],     a0, a1, a2, a3, b0, b1);
                    mma_f16(acc[gi][pr * 2 + 1], a0, a1, a2, a3, b2, b3);
                }
            }
        }
    }

#pragma unroll
    for (int gi = 0; gi < GI; gi++)
#pragma unroll
        for (int ni = 0; ni < 4; ni++) {
            const int n0 = gi * 128 + q * 32 + ni * 8 + 2 * ctg;
            if (row0 + rA < NN)
                *(float2*)(C + (size_t)(row0 + rA) * COLS + n0) =
                    make_float2(acc[gi][ni][0], acc[gi][ni][1]);
            if (row0 + rB < NN)
                *(float2*)(C + (size_t)(row0 + rB) * COLS + n0) =
                    make_float2(acc[gi][ni][2], acc[gi][ni][3]);
        }
}

// ---------------- GAT attention-logit projections (warp per (node, head)) ----------------
template <int NH>
__global__ void gat_al(const float* __restrict__ xh, const float* __restrict__ asrc,
                       const float* __restrict__ adst, float* __restrict__ als,
                       float* __restrict__ ald)
{
    const int w = (blockIdx.x * blockDim.x + threadIdx.x) >> 5;
    const int lane = threadIdx.x & 31;
    if (w >= NN * NH) return;
    const int n = w / NH, h = w % NH;
    const float4 v  = *(const float4*)(xh + (size_t)n * (NH * GHD) + h * GHD + lane * 4);
    const float4 s4 = *(const float4*)(asrc + h * GHD + lane * 4);
    const float4 d4 = *(const float4*)(adst + h * GHD + lane * 4);
    float s = v.x * s4.x + v.y * s4.y + v.z * s4.z + v.w * s4.w;
    float d = v.x * d4.x + v.y * d4.y + v.z * d4.z + v.w * d4.w;
#pragma unroll
    for (int o = 16; o > 0; o >>= 1) {
        s += __shfl_xor_sync(0xffffffffu, s, o);
        d += __shfl_xor_sync(0xffffffffu, d, o);
    }
    if (lane == 0) { als[w] = s; ald[w] = d; }
}

// ---------------- layer-1 gather: warp per (dst, head), lane-parallel edge prologue ------
__global__ void gat_gather4(const float* __restrict__ bias1) {
    const int w = (blockIdx.x * blockDim.x + threadIdx.x) >> 5;
    const int lane = threadIdx.x & 31;
    if (w >= NN * NHEADS) return;
    const int d = w >> 2, h = w & 3;
    const float aldv = g_al1d[d * 4 + h];
    const int beg = g_base[d], end = g_base[d + 1];
    float ax = 0.0f, ay = 0.0f, az = 0.0f, aw = 0.0f, denp = 0.0f;
    for (int eb = beg; eb < end; eb += 32) {
        const int ne = end - eb;
        int sl = 0; float eel = 0.0f;
        if (lane < ne) {
            sl = g_srcs[eb + lane];
            eel = __expf(lrelu(g_al1s[sl * 4 + h] + aldv));
        }
        denp += eel;
        const int m = min(ne, 32);
#pragma unroll 4
        for (int j = 0; j < m; j++) {
            const int s = __shfl_sync(0xffffffffu, sl, j);
            const float ee = __shfl_sync(0xffffffffu, eel, j);
            const float4 v = *(const float4*)(g_xh1 + (size_t)s * 512 + h * GHD + lane * 4);
            ax += ee * v.x; ay += ee * v.y; az += ee * v.z; aw += ee * v.w;
        }
    }
    float den = denp;
#pragma unroll
    for (int o = 16; o > 0; o >>= 1) den += __shfl_xor_sync(0xffffffffu, den, o);
    const float inv = __fdividef(1.0f, den + 1e-16f);
    const float4 b = *(const float4*)(bias1 + h * GHD + lane * 4);
    float4 o;
    o.x = fmaxf(ax * inv + b.x, 0.0f);
    o.y = fmaxf(ay * inv + b.y, 0.0f);
    o.z = fmaxf(az * inv + b.z, 0.0f);
    o.w = fmaxf(aw * inv + b.w, 0.0f);
    *(float4*)(g_agg1 + (size_t)d * 512 + h * GHD + lane * 4) = o;
}

// ---------------- layer-2 gather + fused FC: warp per dst ----------------
__global__ void gat_gather1_fc(const float* __restrict__ bias2,
                               const float* __restrict__ Wfc, const float* __restrict__ bfc,
                               float* __restrict__ out) {
    const int w = (blockIdx.x * blockDim.x + threadIdx.x) >> 5;
    const int lane = threadIdx.x & 31;
    if (w >= NN) return;
    const int d = w;
    const float aldv = g_al2d[d];
    const int beg = g_base[d], end = g_base[d + 1];
    float ax = 0.0f, ay = 0.0f, az = 0.0f, aw = 0.0f, denp = 0.0f;
    for (int eb = beg; eb < end; eb += 32) {
        const int ne = end - eb;
        int sl = 0; float eel = 0.0f;
        if (lane < ne) {
            sl = g_srcs[eb + lane];
            eel = __expf(lrelu(g_al2s[sl] + aldv));
        }
        denp += eel;
        const int m = min(ne, 32);
#pragma unroll 4
        for (int j = 0; j < m; j++) {
            const int s = __shfl_sync(0xffffffffu, sl, j);
            const float ee = __shfl_sync(0xffffffffu, eel, j);
            const float4 v = *(const float4*)(g_xh2 + (size_t)s * 128 + lane * 4);
            ax += ee * v.x; ay += ee * v.y; az += ee * v.z; aw += ee * v.w;
        }
    }
    float den = denp;
#pragma unroll
    for (int o = 16; o > 0; o >>= 1) den += __shfl_xor_sync(0xffffffffu, den, o);
    const float inv = __fdividef(1.0f, den + 1e-16f);
    const float4 b = *(const float4*)(bias2 + lane * 4);
    const float h0 = fmaxf(ax * inv + b.x, 0.0f);
    const float h1 = fmaxf(ay * inv + b.y, 0.0f);
    const float h2 = fmaxf(az * inv + b.z, 0.0f);
    const float h3 = fmaxf(aw * inv + b.w, 0.0f);
#pragma unroll
    for (int c = 0; c < NCLS; c++) {
        const float4 wv = __ldg((const float4*)(Wfc + c * 128 + lane * 4));
        float p = h0 * wv.x + h1 * wv.y + h2 * wv.z + h3 * wv.w;
#pragma unroll
        for (int o = 16; o > 0; o >>= 1) p += __shfl_xor_sync(0xffffffffu, p, o);
        if (lane == 0) out[(size_t)d * NCLS + c] = p + bfc[c];
    }
}

#define GEMM1_SMEM ((64 * 264 + 2 * 512 * SBH) * 2)
#define GEMM2_SMEM ((64 * 520 + 2 * 128 * SBH) * 2)

extern "C" void kernel_launch(void* const* d_in, const int* in_sizes, int n_in,
                              void* d_out, int out_size) {
    const float* x      = (const float*)d_in[0];
    const int*   lens   = (const int*)d_in[1];
    const int*   ei     = (const int*)d_in[2];
    const float* Wih_f  = (const float*)d_in[3];
    const float* Whh_f  = (const float*)d_in[4];
    const float* b_f    = (const float*)d_in[5];
    const float* Wih_b  = (const float*)d_in[6];
    const float* Whh_b  = (const float*)d_in[7];
    const float* b_b    = (const float*)d_in[8];
    const float* W1     = (const float*)d_in[9];
    const float* a1s    = (const float*)d_in[10];
    const float* a1d    = (const float*)d_in[11];
    const float* bias1  = (const float*)d_in[12];
    const float* W2     = (const float*)d_in[13];
    const float* a2s    = (const float*)d_in[14];
    const float* a2d    = (const float*)d_in[15];
    const float* bias2  = (const float*)d_in[16];
    const float* Wfc    = (const float*)d_in[17];
    const float* bfc    = (const float*)d_in[18];
    float* out = (float*)d_out;

    float *p_hcat, *p_xh1, *p_al1s, *p_al1d, *p_agg1, *p_xh2, *p_al2s, *p_al2d;
    __half *p_W1th, *p_W2th;
    cudaGetSymbolAddress((void**)&p_hcat, g_hcat);
    cudaGetSymbolAddress((void**)&p_xh1,  g_xh1);
    cudaGetSymbolAddress((void**)&p_al1s, g_al1s);
    cudaGetSymbolAddress((void**)&p_al1d, g_al1d);
    cudaGetSymbolAddress((void**)&p_agg1, g_agg1);
    cudaGetSymbolAddress((void**)&p_xh2,  g_xh2);
    cudaGetSymbolAddress((void**)&p_al2s, g_al2s);
    cudaGetSymbolAddress((void**)&p_al2d, g_al2d);
    cudaGetSymbolAddress((void**)&p_W1th, g_W1th);
    cudaGetSymbolAddress((void**)&p_W2th, g_W2th);

    cudaFuncSetAttribute(lstm_mma, cudaFuncAttributeMaxDynamicSharedMemorySize, LSTM_SMEM);
    cudaFuncSetAttribute(gemm_mma<256, 512>, cudaFuncAttributeMaxDynamicSharedMemorySize, GEMM1_SMEM);
    cudaFuncSetAttribute(gemm_mma<512, 128>, cudaFuncAttributeMaxDynamicSharedMemorySize, GEMM2_SMEM);

    // launches 0-4 (prep + CSR head), then lstm_mma as launch #5 so ncu -s 5 captures it
    prep_w<<<1024, 256>>>(Wih_f, Whh_f, Wih_b, Whh_b);
    prep_gw<<<(512 * 256 + 128 * 512 + 255) / 256, 256>>>(W1, W2);
    csr_zero<<<(NN + 255) / 256, 256>>>();
    csr_hist<<<(EN + 255) / 256, 256>>>(ei);
    csr_scan<<<1, 1024>>>();

    // BiLSTM (fp16 tensor path, ldmatrix fragments)
    lstm_mma<<<dim3(625, 2), 256, LSTM_SMEM>>>(x, lens, b_f, b_b);

    // CSR scatter (needs csr_scan; only gathers depend on it)
    csr_scatter<<<(EN + 255) / 256, 256>>>(ei);

    // GAT layer 1
    gemm_mma<256, 512><<<313, 512, GEMM1_SMEM>>>(p_hcat, p_W1th, p_xh1);
    gat_al<4><<<NN * 4 / 8, 256>>>(p_xh1, a1s, a1d, p_al1s, p_al1d);
    gat_gather4<<<(NN * 4 + 7) / 8, 256>>>(bias1);

    // GAT layer 2
    gemm_mma<512, 128><<<313, 512, GEMM2_SMEM>>>(p_agg1, p_W2th, p_xh2);
    gat_al<1><<<(NN + 7) / 8, 256>>>(p_xh2, a2s, a2d, p_al2s, p_al2d);
    gat_gather1_fc<<<(NN + 7) / 8, 256>>>(bias2, Wfc, bfc, out);
}